// round 9
// baseline (speedup 1.0000x reference)
#include <cuda_runtime.h>

// Soft-DTW, gamma = 0.01, p = 2, B = 64, M = N = 512.
// One CTA per batch, 512 threads, thread j owns column j.
// Anti-diagonal wavefront with NO per-step barrier:
//   - left neighbor via __shfl_up_sync (intra-warp)
//   - cross-warp boundary via per-pair 512-entry shared window,
//     producer releases a progress counter every 8 steps,
//     consumer prefetches the boundary value one step ahead.
// At step s, thread j computes cell (ii = s - j, j):
//   up   = own r(s-1)          [register]   <- the only serial chain (~64 cyc)
//   left = neighbor r(s-1)     [shfl / shared window]
//   diag = neighbor r(s-2)     [previous left]

#define BIG   1e30f
#define KEXP  144.26950408889634f    // 100 * log2(e)
#define GLN2  0.006931471805599453f  // 0.01 * ln(2)

__device__ __forceinline__ float ex2f_(float v) {
    float r; asm("ex2.approx.ftz.f32 %0, %1;" : "=f"(r) : "f"(v)); return r;
}
__device__ __forceinline__ float lg2f_(float v) {
    float r; asm("lg2.approx.ftz.f32 %0, %1;" : "=f"(r) : "f"(v)); return r;
}
__device__ __forceinline__ int ld_acq(const int* p) {
    int v; asm volatile("ld.acquire.cta.s32 %0, [%1];" : "=r"(v) : "l"(p) : "memory"); return v;
}
__device__ __forceinline__ void st_rel(int* p, int v) {
    asm volatile("st.release.cta.s32 [%0], %1;" :: "l"(p), "r"(v) : "memory");
}

__global__ __launch_bounds__(512, 1)
void softdtw_kernel(const float* __restrict__ x,
                    const float* __restrict__ y,
                    float* __restrict__ out)
{
    __shared__ float ysh[512];
    __shared__ float bnd[15][512];  // bnd[w][ii]: warp w lane-31 (col 32w+31) value at row ii
    __shared__ int   cnt[16];       // cnt[w] = highest step s published by warp w

    const int b    = blockIdx.x;
    const int j    = threadIdx.x;          // column
    const int w    = j >> 5;
    const int lane = j & 31;

    ysh[j] = y[b * 512 + j];
    const float xj = x[b * 512 + j];
    if (j < 16) cnt[j] = -1;
    __syncthreads();                        // the only full barrier

    const int sBeg = 32 * w;
    const int sEnd = 32 * w + 542;          // lane 31 (col 32w+31) last active step

    float rPrev  = BIG;                     // own r(s-1)  (R[-1, j] = +inf)
    float nbPrev = (j == 0) ? 0.0f : BIG;   // neighbor r(s-2); R[-1,-1] = 0 seed

    // y prefetch for first step: ii = sBeg - j = -lane
    float yv = ysh[lane == 0 ? 0 : 511];    // value unused for inactive lanes

    // boundary prefetch for first step (s = sBeg): producer value at step sBeg-1,
    // stored at window index 0. Producer publishes cnt >= 32w-1 at its step 31.
    float bndCur = BIG;
    int avail = -1;
    if (w > 0) {
        while (avail < sBeg - 1) avail = ld_acq(&cnt[w - 1]);
        bndCur = bnd[w - 1][0];
    }

    #pragma unroll 2
    for (int s = sBeg; s <= sEnd; ++s) {
        const int ii = s - j;               // row of this thread's cell

        float nbCur = __shfl_up_sync(0xffffffffu, rPrev, 1);
        if (lane == 0) nbCur = bndCur;

        // softmin3(diag = nbPrev, up = rPrev, left = nbCur) + d
        float t1 = fminf(nbPrev, rPrev);
        float t2 = fmaxf(nbPrev, rPrev);
        float m  = fminf(t1, nbCur);
        float u  = fmaxf(t1, nbCur);
        float d  = xj - yv;
        float mdd = fmaf(d, d, m);          // m + d^2 (off the MUFU chain)
        float mk = m * KEXP;
        float a1 = fminf(fmaf(-KEXP, t2, mk), 0.0f);   // true arg <= 0; clamp fp residue
        float a2 = fminf(fmaf(-KEXP, u,  mk), 0.0f);
        float ss = 1.0f + ex2f_(a1) + ex2f_(a2);
        float r  = fmaf(-GLN2, lg2f_(ss), mdd);
        r = ((unsigned)ii < 512u) ? r : BIG;

        // publish boundary (lane 31 of warps 0..14), window index = row ii
        if (lane == 31 && w < 15 && (unsigned)ii < 512u) bnd[w][ii] = r;
        if (lane == 31 && w < 15 && (s & 7) == 7) st_rel(&cnt[w], s);

        // rotate state
        nbPrev = nbCur;
        rPrev  = r;

        // prefetch y for next step
        yv = ysh[min((unsigned)(ii + 1), 511u)];

        // prefetch boundary for next step (needs producer step s, window index s+1-32w)
        if (w > 0) {
            const int t = s + 1 - sBeg;
            if (t <= 511) {
                if (avail < s) {
                    do { avail = ld_acq(&cnt[w - 1]); } while (avail < s);
                }
                bndCur = bnd[w - 1][t];
            } else {
                bndCur = BIG;               // lane 0 inactive beyond this point
            }
        }
    }

    // unblock any consumer still waiting past our last periodic publish
    if (lane == 31 && w < 15) st_rel(&cnt[w], 0x7FFFFFFF);

    if (j == 511) out[b] = rPrev;           // r at s = 1022 -> R[511,511]
}

extern "C" void kernel_launch(void* const* d_in, const int* in_sizes, int n_in,
                              void* d_out, int out_size)
{
    const float* x = (const float*)d_in[0];
    const float* y = (const float*)d_in[1];
    float* out = (float*)d_out;
    softdtw_kernel<<<64, 512>>>(x, y, out);
}

// round 10
// speedup vs baseline: 1.5391x; 1.5391x over previous
#include <cuda_runtime.h>

// Soft-DTW, gamma = 0.01, p = 2, B = 64, M = N = 512.
// One CTA per batch; 256 threads; thread jj owns columns colA=2jj, colB=2jj+1.
// At global step s, thread jj computes:
//   A = (iiA = s - colA, colA), B = (iiA - 1, colB)
//   B deps: diag=A(s-2), up=B(s-1), left=A(s-1)      -> all registers
//   A deps: diag=nbB(s-2), up=A(s-1), left=nbB(s-1)  -> shfl (lane>0) / mailbox (lane 0)
// Cross-warp boundary: write-once 512-slot mailbox per warp pair; producer lane31
// stores {valueBits, tag=row} as ONE STS.64 (indivisible -> no fence needed);
// consumer prefetches one slot ahead and verifies the tag (uniform-predicate
// asm, no BSSY; spins only when producer hasn't reached that row yet).
// Warp 0 reads a prefilled always-valid dummy row => identical code all warps.

#define BIG   1e30f
#define KEXP  144.26950408889634f    // 100 * log2(e)
#define GLN2  0.006931471805599453f  // 0.01 * ln(2)

__device__ __forceinline__ float ex2f_(float v) {
    float r; asm("ex2.approx.ftz.f32 %0, %1;" : "=f"(r) : "f"(v)); return r;
}
__device__ __forceinline__ float lg2f_(float v) {
    float r; asm("lg2.approx.ftz.f32 %0, %1;" : "=f"(r) : "f"(v)); return r;
}

// softmin3 = m - gamma*ln(1 + e^{(m-v1)/g} + e^{(m-v2)/g})  (R6-proven form)
__device__ __forceinline__ float softmin3(float dg, float up, float lf) {
    float t1 = fminf(dg, up);
    float t2 = fmaxf(dg, up);
    float m  = fminf(t1, lf);
    float u  = fmaxf(t1, lf);
    float mk = m * KEXP;
    float a1 = fmaf(-KEXP, t2, mk);   // <= 0 (+tiny fp residue; selects kill garbage)
    float a2 = fmaf(-KEXP, u,  mk);
    float ss = 1.0f + ex2f_(a1) + ex2f_(a2);
    return fmaf(-GLN2, lg2f_(ss), m);
}

__device__ __forceinline__ uint2 lds_v2_vol(const uint2* p) {
    uint2 r; unsigned a = (unsigned)__cvta_generic_to_shared(p);
    asm volatile("ld.volatile.shared.v2.u32 {%0,%1}, [%2];"
                 : "=r"(r.x), "=r"(r.y) : "r"(a));
    return r;
}
__device__ __forceinline__ void sts_v2_vol(uint2* p, unsigned vx, unsigned vy) {
    unsigned a = (unsigned)__cvta_generic_to_shared(p);
    asm volatile("st.volatile.shared.v2.u32 [%0], {%1,%2};"
                 :: "r"(a), "r"(vx), "r"(vy) : "memory");
}

// Verify prefetched mailbox entry {pre.x=valBits, pre.y=tag} against tag t;
// reload (rare) until the tag matches. Warp-uniform slot => uniform branches.
__device__ __forceinline__ float mb_verify(const uint2* slot, unsigned t, uint2& pre) {
    unsigned a = (unsigned)__cvta_generic_to_shared(slot);
    asm volatile("{\n\t"
        ".reg .pred p;\n\t"
        "setp.eq.u32 p, %1, %2;\n\t"
        "@p bra D%=;\n\t"
        "R%=:\n\t"
        "ld.volatile.shared.v2.u32 {%0,%1}, [%3];\n\t"
        "setp.ne.u32 p, %1, %2;\n\t"
        "@p bra R%=;\n\t"
        "D%=:\n\t"
        "}"
        : "+r"(pre.x), "+r"(pre.y) : "r"(t), "r"(a) : "memory");
    return __uint_as_float(pre.x);
}

__global__ __launch_bounds__(256, 1)
void softdtw_kernel(const float* __restrict__ x,
                    const float* __restrict__ y,
                    float* __restrict__ out)
{
    __shared__ float ysh[512];
    __shared__ uint2 bnd[8][512];   // rows 0..6: mailboxes; row 7: dummy (always valid)

    const int b    = blockIdx.x;
    const int jj   = threadIdx.x;          // 0..255
    const int w    = jj >> 5;
    const int lane = jj & 31;
    const int colA = 2 * jj;
    const int colB = colA + 1;

    ysh[colA] = y[b * 512 + colA];
    ysh[colB] = y[b * 512 + colB];
    const float xA = x[b * 512 + colA];
    const float xB = x[b * 512 + colB];

    // poison tags of real mailboxes; prefill dummy row with {BIG, tag=t}
    {
        uint2* flat = &bnd[0][0];
        for (int t = jj; t < 7 * 512; t += 256) flat[t].y = 0xFFFFFFFFu;
        for (int t = jj; t < 512; t += 256)
            bnd[7][t] = make_uint2(__float_as_uint(BIG), (unsigned)t);
    }
    __syncthreads();                        // the only full barrier

    const uint2* mrow = bnd[(w + 7) & 7];   // w=0 -> dummy row 7; else bnd[w-1]
    uint2*       prow = bnd[w & 7];         // producer row (used only if w<7)
    const bool   isPub = (lane == 31) && (w < 7);

    float aPrev  = BIG;                     // A(s-1)
    float aPrev2 = BIG;                     // A(s-2)
    float bPrev  = BIG;                     // B(s-1)
    float nbPrev = (jj == 0) ? 0.0f : BIG;  // neighbor B(s-2); R[-1,-1]=0 seed

    // y registers: yA = ysh[iiA], yB = ysh[iiA-1]; iiA(t=0) = -2*lane (clamped)
    float yA = ysh[0];
    float yB = ysh[0];

    uint2 pre = lds_v2_vol(&mrow[0]);       // prefetch slot 0

    // ---- phase A: local steps t = 0..511 (mailbox active) ----
    #pragma unroll 2
    for (int t = 0; t < 512; ++t) {
        const int iiA  = t - 2 * lane;      // row of A cell
        const int rowB = iiA - 1;

        float nbCur = __shfl_up_sync(0xffffffffu, bPrev, 1);

        // B cell first: register-only deps, hides mailbox latency
        float dB = xB - yB;
        float rB = fmaf(dB, dB, softmin3(aPrev2, bPrev, aPrev));
        rB = ((unsigned)rowB < 512u) ? rB : BIG;

        // mailbox value for lane 0 (uniform slot/tag across the warp)
        float mv = mb_verify(&mrow[t], (unsigned)t, pre);
        if (lane == 0) nbCur = mv;

        // A cell
        float dA = xA - yA;
        float rA = fmaf(dA, dA, softmin3(nbPrev, aPrev, nbCur));
        rA = ((unsigned)iiA < 512u) ? rA : BIG;

        // publish boundary: ONE indivisible STS.64 {value, tag=row}
        if (isPub && (unsigned)rowB < 512u)
            sts_v2_vol(&prow[rowB], __float_as_uint(rB), (unsigned)rowB);

        // rotate state
        aPrev2 = aPrev;  aPrev = rA;  bPrev = rB;  nbPrev = nbCur;
        yB = yA;
        yA = ysh[min(max(iiA + 1, 0), 511)];

        // prefetch next slot (tag verified next iteration)
        pre = lds_v2_vol(&mrow[min(t + 1, 511)]);
    }

    // ---- phase B: local steps t = 512..574 (lane 0 inactive; no mailbox) ----
    #pragma unroll 2
    for (int t = 512; t <= 574; ++t) {
        const int iiA  = t - 2 * lane;
        const int rowB = iiA - 1;

        float nbCur = __shfl_up_sync(0xffffffffu, bPrev, 1);
        if (lane == 0) nbCur = BIG;

        float dB = xB - yB;
        float rB = fmaf(dB, dB, softmin3(aPrev2, bPrev, aPrev));
        rB = ((unsigned)rowB < 512u) ? rB : BIG;

        float dA = xA - yA;
        float rA = fmaf(dA, dA, softmin3(nbPrev, aPrev, nbCur));
        rA = ((unsigned)iiA < 512u) ? rA : BIG;

        if (isPub && (unsigned)rowB < 512u)
            sts_v2_vol(&prow[rowB], __float_as_uint(rB), (unsigned)rowB);

        aPrev2 = aPrev;  aPrev = rA;  bPrev = rB;  nbPrev = nbCur;
        yB = yA;
        yA = ysh[min(max(iiA + 1, 0), 511)];
    }

    if (jj == 255) out[b] = bPrev;          // B at global step 1022 -> R[511,511]
}

extern "C" void kernel_launch(void* const* d_in, const int* in_sizes, int n_in,
                              void* d_out, int out_size)
{
    const float* x = (const float*)d_in[0];
    const float* y = (const float*)d_in[1];
    float* out = (float*)d_out;
    softdtw_kernel<<<64, 256>>>(x, y, out);
}